// round 1
// baseline (speedup 1.0000x reference)
#include <cuda_runtime.h>
#include <cstddef>

// Problem constants
#define DI  512      // D_IN
#define DM  1024     // D_MEM
#define BB  8        // batch
#define SS  2048     // seq len
#define RR  (BB*SS)  // 16384 rows
#define CS  32       // scan chunk size
#define NCH (SS/CS)  // 64 chunks per batch

// -------- scratch (static device globals; no allocation) --------
__device__ float g_W[DI*DI];           // W = Wo @ Wi   [i][j]
__device__ float g_WiT[DI*DM];         // Wi^T          [j][m]
__device__ float g_c[DI];              // c = Wo @ bi
__device__ float g_y0[BB*DI];          // memory @ Wo^T (init carry)
__device__ float g_v[(size_t)RR*DI];   // v = x @ W^T + c  (32 MB)
__device__ float g_lf[BB*NCH*DI];      // per-chunk local scan finals
__device__ float g_carry[BB*NCH*DI];   // per-chunk carry-in
__device__ float g_part[BB*16*DI];     // partial weighted x sums
__device__ float g_xw[BB*DI];          // weighted x sum

// ---------------------------------------------------------------
// Tiled transpose: in [R][C] -> out [C][R]   (R=1024, C=512)
// ---------------------------------------------------------------
__global__ void transpose_kernel(const float* __restrict__ in, float* __restrict__ out)
{
    __shared__ float tile[32][33];
    int x = blockIdx.x * 32 + threadIdx.x;   // col in 'in' (0..511)
    int y = blockIdx.y * 32 + threadIdx.y;   // row in 'in'
    #pragma unroll
    for (int dy = 0; dy < 32; dy += 8)
        tile[threadIdx.y + dy][threadIdx.x] = in[(size_t)(y + dy) * DI + x];
    __syncthreads();
    int ox = blockIdx.y * 32 + threadIdx.x;  // col in 'out'
    int oy = blockIdx.x * 32 + threadIdx.y;  // row in 'out'
    #pragma unroll
    for (int dy = 0; dy < 32; dy += 8)
        out[(size_t)(oy + dy) * DM + ox] = tile[threadIdx.x][threadIdx.y + dy];
}

// ---------------------------------------------------------------
// SGEMM, both operands K-major: C[m][n] = sum_k A[m*K+k]*B[n*K+k] (+ bias[n])
// ---------------------------------------------------------------
template<int BM, int BN, int BK, int TM, int TN>
__global__ __launch_bounds__((BM/TM)*(BN/TN))
void gemm_tt(const float* __restrict__ A, const float* __restrict__ B,
             float* __restrict__ C, const float* __restrict__ bias,
             int M, int N, int K)
{
    constexpr int NT = (BM/TM) * (BN/TN);
    constexpr int LDA = BK / 4;            // float4 per row segment
    __shared__ float As[BK][BM];
    __shared__ float Bs[BK][BN];

    const int tid = threadIdx.x;
    const int tx  = tid % (BN/TN);
    const int ty  = tid / (BN/TN);
    const int m0  = blockIdx.y * BM;
    const int n0  = blockIdx.x * BN;

    float acc[TM][TN] = {};

    for (int k0 = 0; k0 < K; k0 += BK) {
        for (int idx = tid; idx < BM*BK/4; idx += NT) {
            int row = idx / LDA, kq = idx % LDA;
            float4 a = *(const float4*)&A[(size_t)(m0 + row) * K + k0 + kq*4];
            As[kq*4+0][row] = a.x; As[kq*4+1][row] = a.y;
            As[kq*4+2][row] = a.z; As[kq*4+3][row] = a.w;
        }
        for (int idx = tid; idx < BN*BK/4; idx += NT) {
            int row = idx / LDA, kq = idx % LDA;
            float4 b = *(const float4*)&B[(size_t)(n0 + row) * K + k0 + kq*4];
            Bs[kq*4+0][row] = b.x; Bs[kq*4+1][row] = b.y;
            Bs[kq*4+2][row] = b.z; Bs[kq*4+3][row] = b.w;
        }
        __syncthreads();
        #pragma unroll
        for (int k = 0; k < BK; k++) {
            float af[TM], bf[TN];
            #pragma unroll
            for (int i = 0; i < TM; i++) af[i] = As[k][ty*TM + i];
            #pragma unroll
            for (int j = 0; j < TN; j++) bf[j] = Bs[k][tx*TN + j];
            #pragma unroll
            for (int i = 0; i < TM; i++)
                #pragma unroll
                for (int j = 0; j < TN; j++)
                    acc[i][j] += af[i] * bf[j];
        }
        __syncthreads();
    }

    #pragma unroll
    for (int j = 0; j < TN; j++) {
        int n = n0 + tx*TN + j;
        float vb = bias ? bias[n] : 0.f;
        #pragma unroll
        for (int i = 0; i < TM; i++)
            C[(size_t)(m0 + ty*TM + i) * N + n] = acc[i][j] + vb;
    }
}

// ---------------------------------------------------------------
// c[i] = sum_m Wo[i][m] * bi[m]      (warp per i)
// ---------------------------------------------------------------
__global__ void c_kernel(const float* __restrict__ Wo, const float* __restrict__ bi,
                         float* __restrict__ c)
{
    int w = (blockIdx.x * blockDim.x + threadIdx.x) >> 5;
    int lane = threadIdx.x & 31;
    if (w >= DI) return;
    float s = 0.f;
    for (int m = lane; m < DM; m += 32) s += Wo[(size_t)w * DM + m] * bi[m];
    #pragma unroll
    for (int o = 16; o; o >>= 1) s += __shfl_down_sync(0xffffffffu, s, o);
    if (!lane) c[w] = s;
}

// ---------------------------------------------------------------
// y0[b][i] = sum_m memory[b][m] * Wo[i][m]   (warp per (b,i))
// ---------------------------------------------------------------
__global__ void y0_kernel(const float* __restrict__ mem, const float* __restrict__ Wo,
                          float* __restrict__ y0)
{
    int w = (blockIdx.x * blockDim.x + threadIdx.x) >> 5;
    int lane = threadIdx.x & 31;
    if (w >= BB * DI) return;
    int b = w / DI, i = w % DI;
    float s = 0.f;
    for (int m = lane; m < DM; m += 32) s += mem[(size_t)b * DM + m] * Wo[(size_t)i * DM + m];
    #pragma unroll
    for (int o = 16; o; o >>= 1) s += __shfl_down_sync(0xffffffffu, s, o);
    if (!lane) y0[w] = s;
}

// ---------------------------------------------------------------
// Partial weighted sums for final memory:
//   part[b][ch][j] = sum_{t in chunk} 0.1 * 0.9^(S-1-t) * x[b][t][j]
// chunk = 128 timesteps, 16 chunks.
// ---------------------------------------------------------------
__global__ void xw_part_kernel(const float* __restrict__ x, float* __restrict__ part)
{
    int ch = blockIdx.x;           // 0..15
    int b  = blockIdx.y;           // 0..7
    int j  = threadIdx.x;          // 0..511
    int thi = ch * 128 + 128;      // exclusive upper t
    // weight at t = thi-1 is 0.1 * 0.9^(S-1-(thi-1))
    float w = 0.1f * exp2f((float)(SS - thi) * (-0.15200309344504997f)); // log2(0.9)
    float acc = 0.f;
    const float* xp = x + ((size_t)b * SS + (thi - 1)) * DI + j;
    for (int t = 0; t < 128; t++) {
        acc += w * (*xp);
        w *= 0.9f;
        xp -= DI;
    }
    part[((size_t)b * 16 + ch) * DI + j] = acc;
}

__global__ void xw_red_kernel(const float* __restrict__ part, float* __restrict__ xw)
{
    int b = blockIdx.x, j = threadIdx.x;
    float s = 0.f;
    #pragma unroll
    for (int ch = 0; ch < 16; ch++) s += part[((size_t)b * 16 + ch) * DI + j];
    xw[b * DI + j] = s;
}

// ---------------------------------------------------------------
// final_memory[b][m] = sum_j xw[b][j] * Wi[m][j] + bi[m]
// (bias weight sum = 1 - 0.9^2048 == 1.0f in fp32)
// ---------------------------------------------------------------
__global__ void fm_kernel(const float* __restrict__ xw, const float* __restrict__ Wi,
                          const float* __restrict__ bi, float* __restrict__ fm)
{
    int w = (blockIdx.x * blockDim.x + threadIdx.x) >> 5;
    int lane = threadIdx.x & 31;
    if (w >= BB * DM) return;
    int b = w / DM, m = w % DM;
    float s = 0.f;
    for (int j = lane; j < DI; j += 32) s += xw[b * DI + j] * Wi[(size_t)m * DI + j];
    #pragma unroll
    for (int o = 16; o; o >>= 1) s += __shfl_down_sync(0xffffffffu, s, o);
    if (!lane) fm[w] = s + bi[m];
}

// ---------------------------------------------------------------
// Chunked scan, phase 1: local finals with zero init
// ---------------------------------------------------------------
__global__ void lf_kernel(const float* __restrict__ v, float* __restrict__ lf)
{
    int ch = blockIdx.x, b = blockIdx.y, i = threadIdx.x;
    const float* vp = v + ((size_t)(b * SS + ch * CS)) * DI + i;
    float o = 0.f;
    #pragma unroll
    for (int l = 0; l < CS; l++) o = o * 0.9f + 0.1f * vp[(size_t)l * DI];
    lf[((size_t)b * NCH + ch) * DI + i] = o;
}

// phase 2: sequential carry over chunks (0.9^32 = exact chunk decay)
__global__ void carry_kernel(const float* __restrict__ lf, const float* __restrict__ y0,
                             float* __restrict__ carry)
{
    int b = blockIdx.x, i = threadIdx.x;
    float c = y0[b * DI + i];
    const float P = 0.03433683820292512f;  // 0.9^32
    for (int ch = 0; ch < NCH; ch++) {
        carry[((size_t)b * NCH + ch) * DI + i] = c;
        c = c * P + lf[((size_t)b * NCH + ch) * DI + i];
    }
}

// phase 3: rescan with carry-in, write outputs (+bo)
__global__ void scanout_kernel(const float* __restrict__ v, const float* __restrict__ carry,
                               const float* __restrict__ bo, float* __restrict__ out)
{
    int ch = blockIdx.x, b = blockIdx.y, i = threadIdx.x;
    const size_t base = ((size_t)(b * SS + ch * CS)) * DI + i;
    const float* vp = v + base;
    float*       op = out + base;
    float o = carry[((size_t)b * NCH + ch) * DI + i];
    float bov = bo[i];
    #pragma unroll
    for (int l = 0; l < CS; l++) {
        o = o * 0.9f + 0.1f * vp[(size_t)l * DI];
        op[(size_t)l * DI] = o + bov;
    }
}

// ---------------------------------------------------------------
extern "C" void kernel_launch(void* const* d_in, const int* in_sizes, int n_in,
                              void* d_out, int out_size)
{
    const float* x      = (const float*)d_in[0];  // [B,S,DI]
    const float* memory = (const float*)d_in[1];  // [B,DM]
    const float* Wi     = (const float*)d_in[2];  // [DM,DI]
    const float* bi     = (const float*)d_in[3];  // [DM]
    const float* Wo     = (const float*)d_in[4];  // [DI,DM]
    const float* bo     = (const float*)d_in[5];  // [DI]
    float* out = (float*)d_out;

    float *pW, *pWiT, *pc, *py0, *pv, *plf, *pcar, *ppart, *pxw;
    cudaGetSymbolAddress((void**)&pW,    g_W);
    cudaGetSymbolAddress((void**)&pWiT,  g_WiT);
    cudaGetSymbolAddress((void**)&pc,    g_c);
    cudaGetSymbolAddress((void**)&py0,   g_y0);
    cudaGetSymbolAddress((void**)&pv,    g_v);
    cudaGetSymbolAddress((void**)&plf,   g_lf);
    cudaGetSymbolAddress((void**)&pcar,  g_carry);
    cudaGetSymbolAddress((void**)&ppart, g_part);
    cudaGetSymbolAddress((void**)&pxw,   g_xw);

    // 1) WiT = Wi^T
    transpose_kernel<<<dim3(DI/32, DM/32), dim3(32, 8)>>>(Wi, pWiT);

    // 2) W = Wo @ Wi  (via Wo [512,1024] x WiT [512,1024], K-major both)
    gemm_tt<64,64,8,4,4><<<dim3(DI/64, DI/64), 256>>>(Wo, pWiT, pW, nullptr, DI, DI, DM);

    // 3) c = Wo @ bi ;  y0 = memory @ Wo^T
    c_kernel<<<(DI*32)/256, 256>>>(Wo, bi, pc);
    y0_kernel<<<(BB*DI*32)/256, 256>>>(memory, Wo, py0);

    // 4) v = x @ W^T + c   -- the one big GEMM (16384 x 512 x 512)
    gemm_tt<128,128,8,8,8><<<dim3(DI/128, RR/128), 256>>>(x, pW, pv, pc, RR, DI, DI);

    // 5) final memory path
    xw_part_kernel<<<dim3(16, BB), DI>>>(x, ppart);
    xw_red_kernel<<<BB, DI>>>(ppart, pxw);
    fm_kernel<<<(BB*DM*32)/256, 256>>>(pxw, Wi, bi, out + (size_t)RR * DI);

    // 6) chunked scan over v -> outputs
    lf_kernel<<<dim3(NCH, BB), DI>>>(pv, plf);
    carry_kernel<<<BB, DI>>>(plf, py0, pcar);
    scanout_kernel<<<dim3(NCH, BB), DI>>>(pv, pcar, bo, out);
}

// round 3
// speedup vs baseline: 1.6144x; 1.6144x over previous
#include <cuda_runtime.h>
#include <cuda_bf16.h>
#include <cstdint>
#include <cstddef>

// Problem constants
#define DI  512      // D_IN
#define DM  1024     // D_MEM
#define BB  8        // batch
#define SS  2048     // seq len
#define RR  (BB*SS)  // 16384 rows
#define CS  32       // scan chunk size
#define NCH (SS/CS)  // 64 chunks per batch

// -------- scratch (static device globals; no allocation) --------
__device__ float g_W[DI*DI];                       // W = Wo @ Wi
__device__ float g_WiT[DI*DM];                     // Wi^T
__device__ float g_c[DI];                          // c = Wo @ bi
__device__ float g_y0[BB*DI];                      // memory @ Wo^T
__device__ float g_v[(size_t)RR*DI];               // v = x @ W^T + c
__device__ float g_lf[BB*NCH*DI];
__device__ float g_carry[BB*NCH*DI];
__device__ float g_part[BB*16*DI];
__device__ float g_xw[BB*DI];
__device__ __align__(16) __nv_bfloat16 g_xhi[(size_t)RR*DI];
__device__ __align__(16) __nv_bfloat16 g_xlo[(size_t)RR*DI];
__device__ __align__(16) __nv_bfloat16 g_whi[DI*DI];
__device__ __align__(16) __nv_bfloat16 g_wlo[DI*DI];

// =========================== PTX helpers ===========================
__device__ __forceinline__ uint32_t smem_u32_of(const void* p) {
    uint32_t a;
    asm("{ .reg .u64 t; cvta.to.shared.u64 t, %1; cvt.u32.u64 %0, t; }" : "=r"(a) : "l"(p));
    return a;
}
__device__ __forceinline__ void cp_async16(uint32_t dst, const void* src) {
    asm volatile("cp.async.cg.shared.global [%0], [%1], 16;" :: "r"(dst), "l"(src) : "memory");
}
__device__ __forceinline__ void cp_commit() {
    asm volatile("cp.async.commit_group;" ::: "memory");
}
template<int N> __device__ __forceinline__ void cp_wait() {
    asm volatile("cp.async.wait_group %0;" :: "n"(N) : "memory");
}
__device__ __forceinline__ void ldsm4(uint32_t* r, uint32_t addr) {
    asm volatile("ldmatrix.sync.aligned.m8n8.x4.shared.b16 {%0,%1,%2,%3}, [%4];"
                 : "=r"(r[0]), "=r"(r[1]), "=r"(r[2]), "=r"(r[3]) : "r"(addr));
}
__device__ __forceinline__ void mma16816(float* c, const uint32_t* a, const uint32_t* b) {
    asm volatile(
        "mma.sync.aligned.m16n8k16.row.col.f32.bf16.bf16.f32 "
        "{%0,%1,%2,%3}, {%4,%5,%6,%7}, {%8,%9}, {%0,%1,%2,%3};"
        : "+f"(c[0]), "+f"(c[1]), "+f"(c[2]), "+f"(c[3])
        : "r"(a[0]), "r"(a[1]), "r"(a[2]), "r"(a[3]), "r"(b[0]), "r"(b[1]));
}

// ================== tensor-core GEMM: v = x @ W^T + c ==================
// CTA tile 128x128, BK=32, 8 warps (warp tile 32x64), double-buffered cp.async.
// 3 bf16 products per k-step: xh*Wh + xh*Wl + xl*Wh, fp32 accumulators.
#define KCH    32
#define NCHK   (DI/KCH)          // 16
#define ROWB   80                // padded smem row stride (64B data + 16B pad)
#define MATB   (128*ROWB)        // 10240 bytes per matrix tile
#define STG_B  (4*MATB)          // 40960 per stage (AH,AL,BH,BL)
#define GEMM_SMEM (2*STG_B)      // 81920

__global__ void __launch_bounds__(256)
mma_gemm_kernel(const __nv_bfloat16* __restrict__ xhi, const __nv_bfloat16* __restrict__ xlo,
                const __nv_bfloat16* __restrict__ whi, const __nv_bfloat16* __restrict__ wlo,
                const float* __restrict__ cbias, float* __restrict__ v)
{
    extern __shared__ char smem[];
    const uint32_t sbase = smem_u32_of(smem);
    const int tid  = threadIdx.x;
    const int wid  = tid >> 5;
    const int lane = tid & 31;
    const int wm   = wid & 3;      // 4 m-warps * 32 rows
    const int wn   = wid >> 2;     // 2 n-warps * 64 cols
    const int m0   = blockIdx.y * 128;
    const int n0g  = blockIdx.x * 128;

    const __nv_bfloat16* gp[4] = {
        xhi + (size_t)m0  * DI,
        xlo + (size_t)m0  * DI,
        whi + (size_t)n0g * DI,
        wlo + (size_t)n0g * DI
    };

    // per-lane fragment address offsets (within a [128][ROWB] tile)
    const int lr  = lane & 7;
    const int blk = lane >> 3;
    const uint32_t a_off = (uint32_t)((((blk & 1) * 8 + lr) * ROWB) + ((blk >> 1) * 16));
    const uint32_t b_off = (uint32_t)((((blk >> 1) * 8 + lr) * ROWB) + ((blk & 1) * 16));

    float acc[2][8][4];
    #pragma unroll
    for (int i = 0; i < 2; i++)
        #pragma unroll
        for (int j = 0; j < 8; j++)
            #pragma unroll
            for (int q = 0; q < 4; q++) acc[i][j][q] = 0.f;

    // ---- async stage loader: 2048 x 16B chunks per stage ----
    auto issue = [&](int ch) {
        const int k0 = ch * KCH;
        const uint32_t stg = sbase + (uint32_t)((ch & 1) * STG_B);
        #pragma unroll
        for (int t = 0; t < 8; t++) {
            const int mat = t >> 1;
            const int i   = ((t & 1) << 8) + tid;   // 0..511
            const int row = i >> 2, j = i & 3;
            uint32_t dst = stg + (uint32_t)(mat * MATB + row * ROWB + j * 16);
            cp_async16(dst, gp[mat] + (size_t)row * DI + k0 + j * 8);
        }
        cp_commit();
    };

    issue(0);

    for (int ch = 0; ch < NCHK; ch++) {
        if (ch + 1 < NCHK) issue(ch + 1);
        if (ch + 1 < NCHK) cp_wait<1>(); else cp_wait<0>();
        __syncthreads();

        const uint32_t stg = sbase + (uint32_t)((ch & 1) * STG_B);
        const uint32_t sAH = stg;
        const uint32_t sAL = stg + MATB;
        const uint32_t sBH = stg + 2 * MATB;
        const uint32_t sBL = stg + 3 * MATB;

        #pragma unroll
        for (int kk = 0; kk < 2; kk++) {
            const uint32_t kb = (uint32_t)(kk * 32);
            uint32_t ah[2][4], al[2][4], bh[4][4], bl[4][4];
            #pragma unroll
            for (int mt = 0; mt < 2; mt++) {
                const uint32_t ro = (uint32_t)((wm * 32 + mt * 16) * ROWB) + kb + a_off;
                ldsm4(ah[mt], sAH + ro);
                ldsm4(al[mt], sAL + ro);
            }
            #pragma unroll
            for (int nb = 0; nb < 4; nb++) {
                const uint32_t ro = (uint32_t)((wn * 64 + nb * 16) * ROWB) + kb + b_off;
                ldsm4(bh[nb], sBH + ro);
                ldsm4(bl[nb], sBL + ro);
            }
            #pragma unroll
            for (int mt = 0; mt < 2; mt++)
                #pragma unroll
                for (int nb = 0; nb < 4; nb++) {
                    mma16816(acc[mt][2*nb+0], ah[mt], bh[nb] + 0);
                    mma16816(acc[mt][2*nb+1], ah[mt], bh[nb] + 2);
                    mma16816(acc[mt][2*nb+0], ah[mt], bl[nb] + 0);
                    mma16816(acc[mt][2*nb+1], ah[mt], bl[nb] + 2);
                    mma16816(acc[mt][2*nb+0], al[mt], bh[nb] + 0);
                    mma16816(acc[mt][2*nb+1], al[mt], bh[nb] + 2);
                }
        }
        __syncthreads();
    }

    // ---- epilogue: add bias, store fp32 ----
    #pragma unroll
    for (int mt = 0; mt < 2; mt++) {
        const int grow = m0 + wm * 32 + mt * 16 + (lane >> 2);
        #pragma unroll
        for (int nt = 0; nt < 8; nt++) {
            const int gcol = n0g + wn * 64 + nt * 8 + ((lane & 3) * 2);
            float2 b2 = *(const float2*)(cbias + gcol);
            float2 o0, o1;
            o0.x = acc[mt][nt][0] + b2.x;  o0.y = acc[mt][nt][1] + b2.y;
            o1.x = acc[mt][nt][2] + b2.x;  o1.y = acc[mt][nt][3] + b2.y;
            *(float2*)(v + (size_t)grow * DI + gcol)       = o0;
            *(float2*)(v + (size_t)(grow + 8) * DI + gcol) = o1;
        }
    }
}

// ================== fp32 -> bf16 hi/lo split ==================
__global__ void split_kernel(const float* __restrict__ in, __nv_bfloat16* __restrict__ hi,
                             __nv_bfloat16* __restrict__ lo, int n4)
{
    int i = blockIdx.x * blockDim.x + threadIdx.x;
    if (i >= n4) return;
    float4 v = ((const float4*)in)[i];
    __nv_bfloat16 h[4], l[4];
    float vv[4] = {v.x, v.y, v.z, v.w};
    #pragma unroll
    for (int j = 0; j < 4; j++) {
        h[j] = __float2bfloat16(vv[j]);
        l[j] = __float2bfloat16(vv[j] - __bfloat162float(h[j]));
    }
    *(uint2*)(hi + (size_t)i * 4) = *(uint2*)h;
    *(uint2*)(lo + (size_t)i * 4) = *(uint2*)l;
}

// ================== transpose (Wi -> Wi^T) ==================
__global__ void transpose_kernel(const float* __restrict__ in, float* __restrict__ out)
{
    __shared__ float tile[32][33];
    int x = blockIdx.x * 32 + threadIdx.x;
    int y = blockIdx.y * 32 + threadIdx.y;
    #pragma unroll
    for (int dy = 0; dy < 32; dy += 8)
        tile[threadIdx.y + dy][threadIdx.x] = in[(size_t)(y + dy) * DI + x];
    __syncthreads();
    int ox = blockIdx.y * 32 + threadIdx.x;
    int oy = blockIdx.x * 32 + threadIdx.y;
    #pragma unroll
    for (int dy = 0; dy < 32; dy += 8)
        out[(size_t)(oy + dy) * DM + ox] = tile[threadIdx.x][threadIdx.y + dy];
}

// ================== SIMT gemm for W = Wo @ Wi (small) ==================
template<int BM, int BN, int BK, int TM, int TN>
__global__ __launch_bounds__((BM/TM)*(BN/TN))
void gemm_tt(const float* __restrict__ A, const float* __restrict__ B,
             float* __restrict__ C, const float* __restrict__ bias,
             int M, int N, int K)
{
    constexpr int NT = (BM/TM) * (BN/TN);
    constexpr int LDA = BK / 4;
    __shared__ float As[BK][BM];
    __shared__ float Bs[BK][BN];
    const int tid = threadIdx.x;
    const int tx  = tid % (BN/TN);
    const int ty  = tid / (BN/TN);
    const int m0  = blockIdx.y * BM;
    const int n0  = blockIdx.x * BN;
    float acc[TM][TN] = {};
    for (int k0 = 0; k0 < K; k0 += BK) {
        for (int idx = tid; idx < BM*BK/4; idx += NT) {
            int row = idx / LDA, kq = idx % LDA;
            float4 a = *(const float4*)&A[(size_t)(m0 + row) * K + k0 + kq*4];
            As[kq*4+0][row] = a.x; As[kq*4+1][row] = a.y;
            As[kq*4+2][row] = a.z; As[kq*4+3][row] = a.w;
        }
        for (int idx = tid; idx < BN*BK/4; idx += NT) {
            int row = idx / LDA, kq = idx % LDA;
            float4 b = *(const float4*)&B[(size_t)(n0 + row) * K + k0 + kq*4];
            Bs[kq*4+0][row] = b.x; Bs[kq*4+1][row] = b.y;
            Bs[kq*4+2][row] = b.z; Bs[kq*4+3][row] = b.w;
        }
        __syncthreads();
        #pragma unroll
        for (int k = 0; k < BK; k++) {
            float af[TM], bf[TN];
            #pragma unroll
            for (int i = 0; i < TM; i++) af[i] = As[k][ty*TM + i];
            #pragma unroll
            for (int j = 0; j < TN; j++) bf[j] = Bs[k][tx*TN + j];
            #pragma unroll
            for (int i = 0; i < TM; i++)
                #pragma unroll
                for (int j = 0; j < TN; j++)
                    acc[i][j] += af[i] * bf[j];
        }
        __syncthreads();
    }
    #pragma unroll
    for (int j = 0; j < TN; j++) {
        int n = n0 + tx*TN + j;
        float vb = bias ? bias[n] : 0.f;
        #pragma unroll
        for (int i = 0; i < TM; i++)
            C[(size_t)(m0 + ty*TM + i) * N + n] = acc[i][j] + vb;
    }
}

// ================== small warp-reduce kernels ==================
__global__ void c_kernel(const float* __restrict__ Wo, const float* __restrict__ bi,
                         float* __restrict__ c)
{
    int w = (blockIdx.x * blockDim.x + threadIdx.x) >> 5;
    int lane = threadIdx.x & 31;
    if (w >= DI) return;
    float s = 0.f;
    for (int m = lane; m < DM; m += 32) s += Wo[(size_t)w * DM + m] * bi[m];
    #pragma unroll
    for (int o = 16; o; o >>= 1) s += __shfl_down_sync(0xffffffffu, s, o);
    if (!lane) c[w] = s;
}
__global__ void y0_kernel(const float* __restrict__ mem, const float* __restrict__ Wo,
                          float* __restrict__ y0)
{
    int w = (blockIdx.x * blockDim.x + threadIdx.x) >> 5;
    int lane = threadIdx.x & 31;
    if (w >= BB * DI) return;
    int b = w / DI, i = w % DI;
    float s = 0.f;
    for (int m = lane; m < DM; m += 32) s += mem[(size_t)b * DM + m] * Wo[(size_t)i * DM + m];
    #pragma unroll
    for (int o = 16; o; o >>= 1) s += __shfl_down_sync(0xffffffffu, s, o);
    if (!lane) y0[w] = s;
}

// ================== final-memory path ==================
__global__ void xw_part_kernel(const float* __restrict__ x, float* __restrict__ part)
{
    int ch = blockIdx.x, b = blockIdx.y, j = threadIdx.x;
    int thi = ch * 128 + 128;
    float w = 0.1f * exp2f((float)(SS - thi) * (-0.15200309344504997f));
    float acc = 0.f;
    const float* xp = x + ((size_t)b * SS + (thi - 1)) * DI + j;
    for (int t = 0; t < 128; t++) {
        acc += w * (*xp);
        w *= 0.9f;
        xp -= DI;
    }
    part[((size_t)b * 16 + ch) * DI + j] = acc;
}
__global__ void xw_red_kernel(const float* __restrict__ part, float* __restrict__ xw)
{
    int b = blockIdx.x, j = threadIdx.x;
    float s = 0.f;
    #pragma unroll
    for (int ch = 0; ch < 16; ch++) s += part[((size_t)b * 16 + ch) * DI + j];
    xw[b * DI + j] = s;
}
__global__ void fm_kernel(const float* __restrict__ xw, const float* __restrict__ Wi,
                          const float* __restrict__ bi, float* __restrict__ fm)
{
    int w = (blockIdx.x * blockDim.x + threadIdx.x) >> 5;
    int lane = threadIdx.x & 31;
    if (w >= BB * DM) return;
    int b = w / DM, m = w % DM;
    float s = 0.f;
    for (int j = lane; j < DI; j += 32) s += xw[b * DI + j] * Wi[(size_t)m * DI + j];
    #pragma unroll
    for (int o = 16; o; o >>= 1) s += __shfl_down_sync(0xffffffffu, s, o);
    if (!lane) fm[w] = s + bi[m];
}

// ================== chunked scan ==================
__global__ void lf_kernel(const float* __restrict__ v, float* __restrict__ lf)
{
    int ch = blockIdx.x, b = blockIdx.y, i = threadIdx.x;
    const float* vp = v + ((size_t)(b * SS + ch * CS)) * DI + i;
    float o = 0.f;
    #pragma unroll
    for (int l = 0; l < CS; l++) o = o * 0.9f + 0.1f * vp[(size_t)l * DI];
    lf[((size_t)b * NCH + ch) * DI + i] = o;
}
__global__ void carry_kernel(const float* __restrict__ lf, const float* __restrict__ y0,
                             float* __restrict__ carry)
{
    int b = blockIdx.x, i = threadIdx.x;
    float c = y0[b * DI + i];
    const float P = 0.03433683820292512f;  // 0.9^32
    for (int ch = 0; ch < NCH; ch++) {
        carry[((size_t)b * NCH + ch) * DI + i] = c;
        c = c * P + lf[((size_t)b * NCH + ch) * DI + i];
    }
}
__global__ void scanout_kernel(const float* __restrict__ v, const float* __restrict__ carry,
                               const float* __restrict__ bo, float* __restrict__ out)
{
    int ch = blockIdx.x, b = blockIdx.y, i = threadIdx.x;
    const size_t base = ((size_t)(b * SS + ch * CS)) * DI + i;
    const float* vp = v + base;
    float*       op = out + base;
    float o = carry[((size_t)b * NCH + ch) * DI + i];
    float bov = bo[i];
    #pragma unroll
    for (int l = 0; l < CS; l++) {
        o = o * 0.9f + 0.1f * vp[(size_t)l * DI];
        op[(size_t)l * DI] = o + bov;
    }
}

// ===================================================================
extern "C" void kernel_launch(void* const* d_in, const int* in_sizes, int n_in,
                              void* d_out, int out_size)
{
    const float* x      = (const float*)d_in[0];
    const float* memory = (const float*)d_in[1];
    const float* Wi     = (const float*)d_in[2];
    const float* bi     = (const float*)d_in[3];
    const float* Wo     = (const float*)d_in[4];
    const float* bo     = (const float*)d_in[5];
    float* out = (float*)d_out;

    float *pW, *pWiT, *pc, *py0, *pv, *plf, *pcar, *ppart, *pxw;
    __nv_bfloat16 *pxhi, *pxlo, *pwhi, *pwlo;
    cudaGetSymbolAddress((void**)&pW,    g_W);
    cudaGetSymbolAddress((void**)&pWiT,  g_WiT);
    cudaGetSymbolAddress((void**)&pc,    g_c);
    cudaGetSymbolAddress((void**)&py0,   g_y0);
    cudaGetSymbolAddress((void**)&pv,    g_v);
    cudaGetSymbolAddress((void**)&plf,   g_lf);
    cudaGetSymbolAddress((void**)&pcar,  g_carry);
    cudaGetSymbolAddress((void**)&ppart, g_part);
    cudaGetSymbolAddress((void**)&pxw,   g_xw);
    cudaGetSymbolAddress((void**)&pxhi,  g_xhi);
    cudaGetSymbolAddress((void**)&pxlo,  g_xlo);
    cudaGetSymbolAddress((void**)&pwhi,  g_whi);
    cudaGetSymbolAddress((void**)&pwlo,  g_wlo);

    cudaFuncSetAttribute(mma_gemm_kernel, cudaFuncAttributeMaxDynamicSharedMemorySize, GEMM_SMEM);

    // x -> bf16 hi/lo split (independent of W path)
    split_kernel<<<(RR*DI/4 + 255)/256, 256>>>(x, pxhi, pxlo, RR*DI/4);

    // W = Wo @ Wi (fp32), then split
    transpose_kernel<<<dim3(DI/32, DM/32), dim3(32, 8)>>>(Wi, pWiT);
    gemm_tt<64,64,8,4,4><<<dim3(DI/64, DI/64), 256>>>(Wo, pWiT, pW, nullptr, DI, DI, DM);
    split_kernel<<<(DI*DI/4 + 255)/256, 256>>>(pW, pwhi, pwlo, DI*DI/4);

    // biases / init carry
    c_kernel<<<(DI*32)/256, 256>>>(Wo, bi, pc);
    y0_kernel<<<(BB*DI*32)/256, 256>>>(memory, Wo, py0);

    // big GEMM on tensor cores (mma.sync bf16 split): v = x @ W^T + c
    mma_gemm_kernel<<<dim3(DI/128, RR/128), 256, GEMM_SMEM>>>(pxhi, pxlo, pwhi, pwlo, pc, pv);

    // final-memory path
    xw_part_kernel<<<dim3(16, BB), DI>>>(x, ppart);
    xw_red_kernel<<<BB, DI>>>(ppart, pxw);
    fm_kernel<<<(BB*DM*32)/256, 256>>>(pxw, Wi, bi, out + (size_t)RR * DI);

    // chunked scan over v -> outputs
    lf_kernel<<<dim3(NCH, BB), DI>>>(pv, plf);
    carry_kernel<<<BB, DI>>>(plf, py0, pcar);
    scanout_kernel<<<dim3(NCH, BB), DI>>>(pv, pcar, bo, out);
}

// round 4
// speedup vs baseline: 2.2013x; 1.3636x over previous
#include <cuda_runtime.h>
#include <cuda_bf16.h>
#include <cstdint>
#include <cstddef>

// Problem constants
#define DI  512      // D_IN
#define DM  1024     // D_MEM
#define BB  8        // batch
#define SS  2048     // seq len
#define RR  (BB*SS)  // 16384 rows
#define NCH2 16      // chunks per batch (chunk = 128 steps)

// -------- scratch (static device globals; no allocation) --------
__device__ float g_Wpart[4*DI*DI];                 // split-K partials of W
__device__ float g_WiT[DI*DM];                     // Wi^T
__device__ float g_c[DI];                          // c = Wo @ bi
__device__ float g_y0[BB*DI];                      // memory @ Wo^T
__device__ float g_lf[BB*NCH2*DI];                 // per-chunk scan finals
__device__ float g_carry[BB*NCH2*DI];
__device__ float g_part[BB*16*DI];
__device__ float g_xw[BB*DI];
__device__ __align__(16) __nv_bfloat16 g_whi[DI*DI];
__device__ __align__(16) __nv_bfloat16 g_wlo[DI*DI];

// =========================== PTX helpers ===========================
__device__ __forceinline__ uint32_t smem_u32_of(const void* p) {
    uint32_t a;
    asm("{ .reg .u64 t; cvta.to.shared.u64 t, %1; cvt.u32.u64 %0, t; }" : "=r"(a) : "l"(p));
    return a;
}
__device__ __forceinline__ void cp_async16(uint32_t dst, const void* src) {
    asm volatile("cp.async.cg.shared.global [%0], [%1], 16;" :: "r"(dst), "l"(src) : "memory");
}
__device__ __forceinline__ void cp_commit() {
    asm volatile("cp.async.commit_group;" ::: "memory");
}
template<int N> __device__ __forceinline__ void cp_wait() {
    asm volatile("cp.async.wait_group %0;" :: "n"(N) : "memory");
}
__device__ __forceinline__ void ldsm4(uint32_t* r, uint32_t addr) {
    asm volatile("ldmatrix.sync.aligned.m8n8.x4.shared.b16 {%0,%1,%2,%3}, [%4];"
                 : "=r"(r[0]), "=r"(r[1]), "=r"(r[2]), "=r"(r[3]) : "r"(addr));
}
__device__ __forceinline__ void mma16816(float* c, const uint32_t* a, const uint32_t* b) {
    asm volatile(
        "mma.sync.aligned.m16n8k16.row.col.f32.bf16.bf16.f32 "
        "{%0,%1,%2,%3}, {%4,%5,%6,%7}, {%8,%9}, {%0,%1,%2,%3};"
        : "+f"(c[0]), "+f"(c[1]), "+f"(c[2]), "+f"(c[3])
        : "r"(a[0]), "r"(a[1]), "r"(a[2]), "r"(a[3]), "r"(b[0]), "r"(b[1]));
}

// fp32 x8 -> bf16 hi/lo x8
__device__ __forceinline__ void cvt8(const float4 a, const float4 b, uint4& H, uint4& L) {
    float f[8] = {a.x, a.y, a.z, a.w, b.x, b.y, b.z, b.w};
    uint32_t h[4], l[4];
    #pragma unroll
    for (int q = 0; q < 4; q++) {
        __nv_bfloat162 hh = __floats2bfloat162_rn(f[2*q], f[2*q+1]);
        float r0 = f[2*q]   - __bfloat162float(hh.x);
        float r1 = f[2*q+1] - __bfloat162float(hh.y);
        __nv_bfloat162 ll = __floats2bfloat162_rn(r0, r1);
        h[q] = *(uint32_t*)&hh;
        l[q] = *(uint32_t*)&ll;
    }
    H = make_uint4(h[0], h[1], h[2], h[3]);
    L = make_uint4(l[0], l[1], l[2], l[3]);
}

// ================== fused tensor-core GEMM + scan ==================
// CTA tile 128x128 (128 consecutive timesteps x 128 output cols).
// BK=32, double-buffered; A converted fp32->bf16 hi/lo in-kernel.
// Epilogue: local zero-init scan over 128 steps, +bo, write out; emit lf.
#define KCH    32
#define NCHK   (DI/KCH)          // 16
#define ROWB   80                // padded smem row stride (64B data + 16B pad)
#define MATB   (128*ROWB)        // 10240 bytes per matrix tile
#define STG_B  (4*MATB)          // 40960 per stage (AH,AL,BH,BL)
#define OFF_F  81920             // half-finals: 2*128 floats
#define OFF_BO 82944             // bo strip: 128 floats
#define OFF_CS 83456             // c strip: 128 floats
#define GEMM_SMEM 83968

__global__ void __launch_bounds__(256)
mma_gemm_kernel(const float* __restrict__ x,
                const __nv_bfloat16* __restrict__ whi, const __nv_bfloat16* __restrict__ wlo,
                const float* __restrict__ cbias, const float* __restrict__ bo,
                float* __restrict__ out, float* __restrict__ lf)
{
    extern __shared__ char smem[];
    const uint32_t sbase = smem_u32_of(smem);
    const int tid  = threadIdx.x;
    const int wid  = tid >> 5;
    const int lane = tid & 31;
    const int wm   = wid & 3;      // 4 m-warps * 32 rows
    const int wn   = wid >> 2;     // 2 n-warps * 64 cols
    const int m0   = blockIdx.y * 128;
    const int n0g  = blockIdx.x * 128;
    const int bch  = blockIdx.y;   // b = bch>>4, chunk = bch&15

    float* F_sm  = (float*)(smem + OFF_F);
    float* bo_sm = (float*)(smem + OFF_BO);
    float* cs_sm = (float*)(smem + OFF_CS);
    if (tid < 128) {
        bo_sm[tid] = bo[n0g + tid];
        cs_sm[tid] = cbias[n0g + tid];
    }

    const float* xg = x + (size_t)m0 * DI;
    const __nv_bfloat16* bhg = whi + (size_t)n0g * DI;
    const __nv_bfloat16* blg = wlo + (size_t)n0g * DI;

    // per-lane fragment address offsets (within a [128][ROWB] tile)
    const int lr  = lane & 7;
    const int blk = lane >> 3;
    const uint32_t a_off = (uint32_t)((((blk & 1) * 8 + lr) * ROWB) + ((blk >> 1) * 16));
    const uint32_t b_off = (uint32_t)((((blk >> 1) * 8 + lr) * ROWB) + ((blk & 1) * 16));

    float acc[2][8][4];
    #pragma unroll
    for (int i = 0; i < 2; i++)
        #pragma unroll
        for (int j = 0; j < 8; j++)
            #pragma unroll
            for (int q = 0; q < 4; q++) acc[i][j][q] = 0.f;

    float4 xr[4];

    // prefetch A fp32 for a chunk into registers
    auto ldA = [&](int ch) {
        const int k0 = ch * KCH;
        #pragma unroll
        for (int u = 0; u < 2; u++) {
            const int idx2 = tid * 2 + u;
            const int r = idx2 >> 2, j = idx2 & 3;
            const float4* sp = (const float4*)(xg + (size_t)r * DI + k0 + j * 8);
            xr[u*2+0] = sp[0];
            xr[u*2+1] = sp[1];
        }
    };
    // convert registers -> bf16 hi/lo smem tiles
    auto stA = [&](int ch) {
        const uint32_t stg = (uint32_t)((ch & 1) * STG_B);
        #pragma unroll
        for (int u = 0; u < 2; u++) {
            const int idx2 = tid * 2 + u;
            const int r = idx2 >> 2, j = idx2 & 3;
            uint4 H, L;
            cvt8(xr[u*2+0], xr[u*2+1], H, L);
            *(uint4*)(smem + stg + r * ROWB + j * 16)        = H;
            *(uint4*)(smem + stg + MATB + r * ROWB + j * 16) = L;
        }
    };
    // cp.async B hi/lo tiles (from pre-split W)
    auto issueB = [&](int ch) {
        const int k0 = ch * KCH;
        const uint32_t stg = sbase + (uint32_t)((ch & 1) * STG_B);
        #pragma unroll
        for (int t = 0; t < 4; t++) {
            const int mat = 2 + (t >> 1);
            const int i   = ((t & 1) << 8) + tid;
            const int row = i >> 2, j = i & 3;
            const uint32_t dst = stg + (uint32_t)(mat * MATB + row * ROWB + j * 16);
            const __nv_bfloat16* src = (mat == 2 ? bhg : blg) + (size_t)row * DI + k0 + j * 8;
            cp_async16(dst, src);
        }
        cp_commit();
    };

    ldA(0);
    issueB(0);

    for (int ch = 0; ch < NCHK; ch++) {
        if (ch + 1 < NCHK) issueB(ch + 1);   // overlaps MMA(ch)
        stA(ch);
        if (ch + 1 < NCHK) ldA(ch + 1);      // LDG prefetch overlaps wait+MMA
        if (ch + 1 < NCHK) cp_wait<1>(); else cp_wait<0>();
        __syncthreads();

        const uint32_t stg = sbase + (uint32_t)((ch & 1) * STG_B);
        const uint32_t sAH = stg;
        const uint32_t sAL = stg + MATB;
        const uint32_t sBH = stg + 2 * MATB;
        const uint32_t sBL = stg + 3 * MATB;

        #pragma unroll
        for (int kk = 0; kk < 2; kk++) {
            const uint32_t kb = (uint32_t)(kk * 32);
            uint32_t ah[2][4], al[2][4], bh[4][4], bl[4][4];
            #pragma unroll
            for (int mt = 0; mt < 2; mt++) {
                const uint32_t ro = (uint32_t)((wm * 32 + mt * 16) * ROWB) + kb + a_off;
                ldsm4(ah[mt], sAH + ro);
                ldsm4(al[mt], sAL + ro);
            }
            #pragma unroll
            for (int nb = 0; nb < 4; nb++) {
                const uint32_t ro = (uint32_t)((wn * 64 + nb * 16) * ROWB) + kb + b_off;
                ldsm4(bh[nb], sBH + ro);
                ldsm4(bl[nb], sBL + ro);
            }
            #pragma unroll
            for (int mt = 0; mt < 2; mt++)
                #pragma unroll
                for (int nb = 0; nb < 4; nb++) {
                    mma16816(acc[mt][2*nb+0], ah[mt], bh[nb] + 0);
                    mma16816(acc[mt][2*nb+1], ah[mt], bh[nb] + 2);
                    mma16816(acc[mt][2*nb+0], ah[mt], bl[nb] + 0);
                    mma16816(acc[mt][2*nb+1], ah[mt], bl[nb] + 2);
                    mma16816(acc[mt][2*nb+0], al[mt], bh[nb] + 0);
                    mma16816(acc[mt][2*nb+1], al[mt], bh[nb] + 2);
                }
        }
        __syncthreads();
    }

    // ---- epilogue: dump acc to smem, local scan, +bo, write out ----
    float* S = (float*)smem;   // [128][132] fp32
    #pragma unroll
    for (int mt = 0; mt < 2; mt++) {
        const int r0 = wm * 32 + mt * 16 + (lane >> 2);
        #pragma unroll
        for (int nt = 0; nt < 8; nt++) {
            const int c0 = wn * 64 + nt * 8 + ((lane & 3) * 2);
            S[r0 * 132 + c0]       = acc[mt][nt][0];
            S[r0 * 132 + c0 + 1]   = acc[mt][nt][1];
            S[(r0+8) * 132 + c0]     = acc[mt][nt][2];
            S[(r0+8) * 132 + c0 + 1] = acc[mt][nt][3];
        }
    }
    __syncthreads();

    // two-half scan (zero init), v = acc + c
    const int col  = tid & 127;
    const int half = tid >> 7;
    const float cv = cs_sm[col];
    {
        const int tb = half * 64;
        float o = 0.f;
        #pragma unroll 4
        for (int t = 0; t < 64; t++) {
            o = o * 0.9f + 0.1f * (S[(tb + t) * 132 + col] + cv);
            S[(tb + t) * 132 + col] = o;
        }
        F_sm[half * 128 + col] = o;
    }
    __syncthreads();

    if (half == 1) {
        const float f0 = F_sm[col];   // half-0 final
        float p = 0.9f, last = 0.f;
        #pragma unroll 4
        for (int t = 0; t < 64; t++) {
            last = S[(64 + t) * 132 + col] + p * f0;
            S[(64 + t) * 132 + col] = last;
            p *= 0.9f;
        }
        lf[(size_t)bch * DI + n0g + col] = last;   // chunk-final (zero-init)
    }
    __syncthreads();

    // write out + bo (coalesced float4)
    #pragma unroll
    for (int it = 0; it < 16; it++) {
        const int idx = tid + it * 256;       // 0..4095
        const int row = idx >> 5;
        const int q   = idx & 31;
        float4 s = *(float4*)&S[row * 132 + q * 4];
        const int lc = q * 4;
        s.x += bo_sm[lc]; s.y += bo_sm[lc+1]; s.z += bo_sm[lc+2]; s.w += bo_sm[lc+3];
        *(float4*)(out + (size_t)(m0 + row) * DI + n0g + lc) = s;
    }
}

// ================== carry + fixup for the chunked scan ==================
__global__ void carry_kernel(const float* __restrict__ lf, const float* __restrict__ y0,
                             float* __restrict__ carry)
{
    const int b = blockIdx.x, i = threadIdx.x;
    float c = y0[b * DI + i];
    const float P = 1.3900845237714473e-06f;   // 0.9^128
    for (int ch = 0; ch < NCH2; ch++) {
        carry[(size_t)(b * NCH2 + ch) * DI + i] = c;
        c = c * P + lf[(size_t)(b * NCH2 + ch) * DI + i];
    }
}
__global__ void fixup_kernel(const float* __restrict__ carry, float* __restrict__ out)
{
    const int ch = blockIdx.x, b = blockIdx.y, i = threadIdx.x;
    const float cr = carry[(size_t)(b * NCH2 + ch) * DI + i];
    if (cr == 0.f) return;
    float p = 0.9f;
    float* op = out + (size_t)(b * SS + ch * 128) * DI + i;
    #pragma unroll 4
    for (int t = 0; t < 128; t++) {
        op[(size_t)t * DI] += p * cr;
        p *= 0.9f;
    }
}

// ================== transpose (Wi -> Wi^T) ==================
__global__ void transpose_kernel(const float* __restrict__ in, float* __restrict__ out)
{
    __shared__ float tile[32][33];
    int xx = blockIdx.x * 32 + threadIdx.x;
    int yy = blockIdx.y * 32 + threadIdx.y;
    #pragma unroll
    for (int dy = 0; dy < 32; dy += 8)
        tile[threadIdx.y + dy][threadIdx.x] = in[(size_t)(yy + dy) * DI + xx];
    __syncthreads();
    int ox = blockIdx.y * 32 + threadIdx.x;
    int oy = blockIdx.x * 32 + threadIdx.y;
    #pragma unroll
    for (int dy = 0; dy < 32; dy += 8)
        out[(size_t)(oy + dy) * DM + ox] = tile[threadIdx.x][threadIdx.y + dy];
}

// ================== W = Wo @ Wi, split-K=4 partials ==================
__global__ void __launch_bounds__(256)
wgemm_kernel(const float* __restrict__ A, const float* __restrict__ B,
             float* __restrict__ Wpart)
{
    __shared__ float As[8][64];
    __shared__ float Bs[8][64];
    const int tid = threadIdx.x;
    const int tx  = tid % 16;
    const int ty  = tid / 16;
    const int m0  = blockIdx.y * 64;
    const int n0  = blockIdx.x * 64;
    const int ks  = blockIdx.z * 256;
    float acc[4][4] = {};
    for (int k0 = ks; k0 < ks + 256; k0 += 8) {
        const int idx = tid;   // 128 items needed, 256 threads
        if (idx < 128) {
            const int row = idx >> 1, kq = idx & 1;
            float4 a = *(const float4*)&A[(size_t)(m0 + row) * DM + k0 + kq*4];
            As[kq*4+0][row] = a.x; As[kq*4+1][row] = a.y;
            As[kq*4+2][row] = a.z; As[kq*4+3][row] = a.w;
        } else {
            const int i2 = idx - 128;
            const int row = i2 >> 1, kq = i2 & 1;
            float4 b = *(const float4*)&B[(size_t)(n0 + row) * DM + k0 + kq*4];
            Bs[kq*4+0][row] = b.x; Bs[kq*4+1][row] = b.y;
            Bs[kq*4+2][row] = b.z; Bs[kq*4+3][row] = b.w;
        }
        __syncthreads();
        #pragma unroll
        for (int k = 0; k < 8; k++) {
            float af[4], bf[4];
            #pragma unroll
            for (int i = 0; i < 4; i++) af[i] = As[k][ty*4 + i];
            #pragma unroll
            for (int j = 0; j < 4; j++) bf[j] = Bs[k][tx*4 + j];
            #pragma unroll
            for (int i = 0; i < 4; i++)
                #pragma unroll
                for (int j = 0; j < 4; j++)
                    acc[i][j] += af[i] * bf[j];
        }
        __syncthreads();
    }
    float* Co = Wpart + (size_t)blockIdx.z * DI * DI;
    #pragma unroll
    for (int i = 0; i < 4; i++)
        #pragma unroll
        for (int j = 0; j < 4; j++)
            Co[(size_t)(m0 + ty*4 + i) * DI + n0 + tx*4 + j] = acc[i][j];
}

// ============ sum split-K partials -> bf16 hi/lo; also c = Wo@bi ============
__global__ void splitwc_kernel(const float* __restrict__ Wpart,
                               __nv_bfloat16* __restrict__ whi, __nv_bfloat16* __restrict__ wlo,
                               const float* __restrict__ Wo, const float* __restrict__ bi,
                               float* __restrict__ c)
{
    const int blk = blockIdx.x;
    const int tid = threadIdx.x;
    if (blk < 256) {
        const int i = blk * 256 + tid;     // float4 index over 512*512/4
        float4 s = ((const float4*)Wpart)[i];
        #pragma unroll
        for (int p = 1; p < 4; p++) {
            float4 t = ((const float4*)(Wpart + (size_t)p * DI * DI))[i];
            s.x += t.x; s.y += t.y; s.z += t.z; s.w += t.w;
        }
        __nv_bfloat162 h0 = __floats2bfloat162_rn(s.x, s.y);
        __nv_bfloat162 h1 = __floats2bfloat162_rn(s.z, s.w);
        __nv_bfloat162 l0 = __floats2bfloat162_rn(s.x - __bfloat162float(h0.x), s.y - __bfloat162float(h0.y));
        __nv_bfloat162 l1 = __floats2bfloat162_rn(s.z - __bfloat162float(h1.x), s.w - __bfloat162float(h1.y));
        uint2 H = make_uint2(*(uint32_t*)&h0, *(uint32_t*)&h1);
        uint2 L = make_uint2(*(uint32_t*)&l0, *(uint32_t*)&l1);
        *(uint2*)(whi + (size_t)i * 4) = H;
        *(uint2*)(wlo + (size_t)i * 4) = L;
    } else {
        const int w = (blk - 256) * 8 + (tid >> 5);   // 64 blocks * 8 warps = 512
        const int lane = tid & 31;
        float s = 0.f;
        for (int m = lane; m < DM; m += 32) s += Wo[(size_t)w * DM + m] * bi[m];
        #pragma unroll
        for (int o = 16; o; o >>= 1) s += __shfl_down_sync(0xffffffffu, s, o);
        if (!lane) c[w] = s;
    }
}

// ================== y0 = memory @ Wo^T ==================
__global__ void y0_kernel(const float* __restrict__ mem, const float* __restrict__ Wo,
                          float* __restrict__ y0)
{
    int w = (blockIdx.x * blockDim.x + threadIdx.x) >> 5;
    int lane = threadIdx.x & 31;
    if (w >= BB * DI) return;
    int b = w / DI, i = w % DI;
    float s = 0.f;
    for (int m = lane; m < DM; m += 32) s += mem[(size_t)b * DM + m] * Wo[(size_t)i * DM + m];
    #pragma unroll
    for (int o = 16; o; o >>= 1) s += __shfl_down_sync(0xffffffffu, s, o);
    if (!lane) y0[w] = s;
}

// ================== final-memory path ==================
__global__ void xw_part_kernel(const float* __restrict__ x, float* __restrict__ part)
{
    int ch = blockIdx.x, b = blockIdx.y, j = threadIdx.x;
    int thi = ch * 128 + 128;
    float w = 0.1f * exp2f((float)(SS - thi) * (-0.15200309344504997f));
    float acc = 0.f;
    const float* xp = x + ((size_t)b * SS + (thi - 1)) * DI + j;
    for (int t = 0; t < 128; t++) {
        acc += w * (*xp);
        w *= 0.9f;
        xp -= DI;
    }
    part[((size_t)b * 16 + ch) * DI + j] = acc;
}
__global__ void xw_red_kernel(const float* __restrict__ part, float* __restrict__ xw)
{
    int b = blockIdx.x, j = threadIdx.x;
    float s = 0.f;
    #pragma unroll
    for (int ch = 0; ch < 16; ch++) s += part[((size_t)b * 16 + ch) * DI + j];
    xw[b * DI + j] = s;
}
__global__ void fm_kernel(const float* __restrict__ xw, const float* __restrict__ Wi,
                          const float* __restrict__ bi, float* __restrict__ fm)
{
    int w = (blockIdx.x * blockDim.x + threadIdx.x) >> 5;
    int lane = threadIdx.x & 31;
    if (w >= BB * DM) return;
    int b = w / DM, m = w % DM;
    float s = 0.f;
    for (int j = lane; j < DI; j += 32) s += xw[b * DI + j] * Wi[(size_t)m * DI + j];
    #pragma unroll
    for (int o = 16; o; o >>= 1) s += __shfl_down_sync(0xffffffffu, s, o);
    if (!lane) fm[w] = s + bi[m];
}

// ===================================================================
extern "C" void kernel_launch(void* const* d_in, const int* in_sizes, int n_in,
                              void* d_out, int out_size)
{
    const float* x      = (const float*)d_in[0];
    const float* memory = (const float*)d_in[1];
    const float* Wi     = (const float*)d_in[2];
    const float* bi     = (const float*)d_in[3];
    const float* Wo     = (const float*)d_in[4];
    const float* bo     = (const float*)d_in[5];
    float* out = (float*)d_out;

    float *pWpart, *pWiT, *pc, *py0, *plf, *pcar, *ppart, *pxw;
    __nv_bfloat16 *pwhi, *pwlo;
    cudaGetSymbolAddress((void**)&pWpart, g_Wpart);
    cudaGetSymbolAddress((void**)&pWiT,   g_WiT);
    cudaGetSymbolAddress((void**)&pc,     g_c);
    cudaGetSymbolAddress((void**)&py0,    g_y0);
    cudaGetSymbolAddress((void**)&plf,    g_lf);
    cudaGetSymbolAddress((void**)&pcar,   g_carry);
    cudaGetSymbolAddress((void**)&ppart,  g_part);
    cudaGetSymbolAddress((void**)&pxw,    g_xw);
    cudaGetSymbolAddress((void**)&pwhi,   g_whi);
    cudaGetSymbolAddress((void**)&pwlo,   g_wlo);

    cudaFuncSetAttribute(mma_gemm_kernel, cudaFuncAttributeMaxDynamicSharedMemorySize, GEMM_SMEM);

    // idx 0: Wi^T
    transpose_kernel<<<dim3(DI/32, DM/32), dim3(32, 8)>>>(Wi, pWiT);
    // idx 1: W = Wo @ Wi split-K partials
    wgemm_kernel<<<dim3(8, 8, 4), 256>>>(Wo, pWiT, pWpart);
    // idx 2: sum partials -> bf16 hi/lo split; c = Wo @ bi
    splitwc_kernel<<<320, 256>>>(pWpart, pwhi, pwlo, Wo, bi, pc);
    // idx 3: fused GEMM + local scan (profiled slot)
    mma_gemm_kernel<<<dim3(DI/128, RR/128), 256, GEMM_SMEM>>>(x, pwhi, pwlo, pc, bo, out, plf);
    // idx 4: y0 = memory @ Wo^T
    y0_kernel<<<(BB*DI*32)/256, 256>>>(memory, Wo, py0);
    // idx 5-7: final-memory path
    xw_part_kernel<<<dim3(16, BB), DI>>>(x, ppart);
    xw_red_kernel<<<BB, DI>>>(ppart, pxw);
    fm_kernel<<<(BB*DM*32)/256, 256>>>(pxw, Wi, bi, out + (size_t)RR * DI);
    // idx 8-9: cross-chunk carry + fixup
    carry_kernel<<<BB, DI>>>(plf, py0, pcar);
    fixup_kernel<<<dim3(NCH2, BB), DI>>>(pcar, out);
}